// round 11
// baseline (speedup 1.0000x reference)
#include <cuda_runtime.h>
#include <cstdint>

// ---------------------------------------------------------------------------
// AttentionMapLayer: out[b,h,w,c] = (t_hat[b,h]*s_hat[b,w] + roi[w]) * ipt[b,h,w,c]
//   s_hat = l2_normalize(s_o, axis=1)  (B,25)
//   t_hat = l2_normalize(t_o, axis=1)  (B,300)
//   roi[w] = 1 for w in {3,8,12,14,17,19}, else 0
// B=1024, H=300, W=25, C=16  -> out = 122.88M f32 (491.5 MB)
// Pure streaming: ~983 MB HBM traffic, target ~160 us.
// ---------------------------------------------------------------------------

#define HEIGHT 300
#define WIDTH  25
#define CHANS  16
#define MAX_B  4096

// roi bitmask over w in [0,25)
#define ROI_MASK ((1u<<3)|(1u<<8)|(1u<<12)|(1u<<14)|(1u<<17)|(1u<<19))

// Scratch for normalized vectors (device globals: allocation-guard safe)
__device__ float g_s_hat[MAX_B * WIDTH];
__device__ float g_t_hat[MAX_B * HEIGHT];

// ---------------------------------------------------------------------------
// Kernel 1: per-batch L2 normalization of s_o (25) and t_o (300).
// One block per batch, 128 threads. Cost is negligible vs. the stream.
// ---------------------------------------------------------------------------
__global__ __launch_bounds__(128)
void normalize_kernel(const float* __restrict__ s_o,
                      const float* __restrict__ t_o)
{
    const int b   = blockIdx.x;
    const int tid = threadIdx.x;

    __shared__ float red[4];  // one slot per warp (128 thr = 4 warps)

    // ---- sum of squares for t_o (300 elems) and s_o (25 elems), fused ----
    float acc_t = 0.0f;
    for (int i = tid; i < HEIGHT; i += 128) {
        float v = t_o[b * HEIGHT + i];
        acc_t += v * v;
    }
    float acc_s = 0.0f;
    if (tid < WIDTH) {
        float v = s_o[b * WIDTH + tid];
        acc_s = v * v;
    }

    // warp reduce
    #pragma unroll
    for (int off = 16; off > 0; off >>= 1) {
        acc_t += __shfl_down_sync(0xffffffffu, acc_t, off);
        acc_s += __shfl_down_sync(0xffffffffu, acc_s, off);
    }
    const int warp = tid >> 5;
    const int lane = tid & 31;
    if (lane == 0) red[warp] = acc_t;
    __syncthreads();
    float sum_t = red[0] + red[1] + red[2] + red[3];
    // acc_s lives entirely in warp 0 (tid<25); its lane-0 holds the full sum.
    __shared__ float s_sum_sh;
    if (tid == 0) s_sum_sh = acc_s;
    __syncthreads();
    float sum_s = s_sum_sh;

    const float inv_t = rsqrtf(fmaxf(sum_t, 1e-12f));
    const float inv_s = rsqrtf(fmaxf(sum_s, 1e-12f));

    // ---- write normalized values ----
    for (int i = tid; i < HEIGHT; i += 128)
        g_t_hat[b * HEIGHT + i] = t_o[b * HEIGHT + i] * inv_t;
    if (tid < WIDTH)
        g_s_hat[b * WIDTH + tid] = s_o[b * WIDTH + tid] * inv_s;
}

// ---------------------------------------------------------------------------
// Kernel 2: streaming multiply. One float4 per thread (4 channels).
// 4 float4 per (b,h,w) triple since C=16. Scale operands are L1/L2-resident.
// ---------------------------------------------------------------------------
__global__ __launch_bounds__(256)
void scale_mul_kernel(const float4* __restrict__ ipt,
                      float4* __restrict__ out,
                      int total4)
{
    int i = blockIdx.x * 256 + threadIdx.x;
    if (i >= total4) return;

    const int p  = i >> 2;          // linear (b,h,w) index
    const int w  = p % WIDTH;       // magic-mul, cheap
    const int bh = p / WIDTH;       // b*HEIGHT + h
    const int b  = bh / HEIGHT;

    const float roi   = (ROI_MASK >> w) & 1u ? 1.0f : 0.0f;
    const float scale = fmaf(__ldg(&g_t_hat[bh]),
                             __ldg(&g_s_hat[b * WIDTH + w]),
                             roi);

    float4 v = ipt[i];
    v.x *= scale; v.y *= scale; v.z *= scale; v.w *= scale;
    out[i] = v;
}

// ---------------------------------------------------------------------------
// Launch
// ---------------------------------------------------------------------------
extern "C" void kernel_launch(void* const* d_in, const int* in_sizes, int n_in,
                              void* d_out, int out_size)
{
    // Identify inputs by size (robust to metadata ordering):
    //   ipt   = B*300*25*16  (largest)
    //   t_o   = B*300
    //   s_o   = B*25
    int ipt_i = 0;
    for (int k = 1; k < n_in; ++k)
        if (in_sizes[k] > in_sizes[ipt_i]) ipt_i = k;
    int a = -1, c = -1;
    for (int k = 0; k < n_in; ++k) {
        if (k == ipt_i) continue;
        if (a < 0) a = k; else c = k;
    }
    // smaller of the two remaining is s_o
    int s_i = (in_sizes[a] < in_sizes[c]) ? a : c;
    int t_i = (s_i == a) ? c : a;

    const float* s_o = (const float*)d_in[s_i];
    const float* t_o = (const float*)d_in[t_i];
    const float* ipt = (const float*)d_in[ipt_i];
    float* out = (float*)d_out;

    const int B = in_sizes[t_i] / HEIGHT;   // 1024

    // Kernel 1: normalize (B blocks x 128 threads)
    normalize_kernel<<<B, 128>>>(s_o, t_o);

    // Kernel 2: stream (one float4 per thread)
    const int total4 = out_size / 4;        // B*300*25*16 / 4
    const int blocks = (total4 + 255) / 256;
    scale_mul_kernel<<<blocks, 256>>>((const float4*)ipt, (float4*)out, total4);
}

// round 12
// speedup vs baseline: 1.0456x; 1.0456x over previous
#include <cuda_runtime.h>
#include <cstdint>

// ---------------------------------------------------------------------------
// AttentionMapLayer: out[b,h,w,c] = (t_hat[b,h]*s_hat[b,w] + roi[w]) * ipt[b,h,w,c]
//   s_hat = l2_normalize(s_o, axis=1)  (B,25)
//   t_hat = l2_normalize(t_o, axis=1)  (B,300)
//   roi[w] = 1 for w in {3,8,12,14,17,19}, else 0
// B=1024, H=300, W=25, C=16  -> 983 MB HBM traffic, floor ~150 us @ ~6.5 TB/s.
// R12: 4 float4 per thread, front-batched loads (MLP_p1=4) to push DRAM% up.
// ---------------------------------------------------------------------------

#define HEIGHT 300
#define WIDTH  25
#define CHANS  16
#define MAX_B  4096

// roi bitmask over w in [0,25)
#define ROI_MASK ((1u<<3)|(1u<<8)|(1u<<12)|(1u<<14)|(1u<<17)|(1u<<19))

// Scratch for normalized vectors (device globals: allocation-guard safe)
__device__ float g_s_hat[MAX_B * WIDTH];
__device__ float g_t_hat[MAX_B * HEIGHT];

// ---------------------------------------------------------------------------
// Kernel 1: per-batch L2 normalization of s_o (25) and t_o (300).
// One block per batch, 128 threads. ~1 wave, latency-bound, negligible cost.
// ---------------------------------------------------------------------------
__global__ __launch_bounds__(128)
void normalize_kernel(const float* __restrict__ s_o,
                      const float* __restrict__ t_o)
{
    const int b   = blockIdx.x;
    const int tid = threadIdx.x;

    __shared__ float red[4];  // one slot per warp (128 thr = 4 warps)

    // ---- sum of squares for t_o (300 elems) and s_o (25 elems), fused ----
    float acc_t = 0.0f;
    for (int i = tid; i < HEIGHT; i += 128) {
        float v = t_o[b * HEIGHT + i];
        acc_t += v * v;
    }
    float acc_s = 0.0f;
    if (tid < WIDTH) {
        float v = s_o[b * WIDTH + tid];
        acc_s = v * v;
    }

    // warp reduce
    #pragma unroll
    for (int off = 16; off > 0; off >>= 1) {
        acc_t += __shfl_down_sync(0xffffffffu, acc_t, off);
        acc_s += __shfl_down_sync(0xffffffffu, acc_s, off);
    }
    const int warp = tid >> 5;
    const int lane = tid & 31;
    if (lane == 0) red[warp] = acc_t;
    __syncthreads();
    float sum_t = red[0] + red[1] + red[2] + red[3];
    // acc_s lives entirely in warp 0 (tid<25); its lane-0 holds the full sum.
    __shared__ float s_sum_sh;
    if (tid == 0) s_sum_sh = acc_s;
    __syncthreads();
    float sum_s = s_sum_sh;

    const float inv_t = rsqrtf(fmaxf(sum_t, 1e-12f));
    const float inv_s = rsqrtf(fmaxf(sum_s, 1e-12f));

    // ---- write normalized values ----
    for (int i = tid; i < HEIGHT; i += 128)
        g_t_hat[b * HEIGHT + i] = t_o[b * HEIGHT + i] * inv_t;
    if (tid < WIDTH)
        g_s_hat[b * WIDTH + tid] = s_o[b * WIDTH + tid] * inv_s;
}

// ---------------------------------------------------------------------------
// Kernel 2: streaming multiply, 4 float4s per thread (block-strided so every
// LDG.128 / STG.128 stays perfectly coalesced: warp covers 512B contiguous).
// Phase 1: issue all 4 main loads (independent, front-batched -> MLP_p1=4).
// Phase 2: issue all scale lookups (L1/L2-resident, high reuse).
// Phase 3: FMA + stores.
// ---------------------------------------------------------------------------
#define ITEMS 4
#define BLKTHREADS 256
#define TILE4 (BLKTHREADS * ITEMS)   // 1024 float4 per block

__global__ __launch_bounds__(BLKTHREADS)
void scale_mul_kernel(const float4* __restrict__ ipt,
                      float4* __restrict__ out,
                      int total4)
{
    const int base = blockIdx.x * TILE4 + threadIdx.x;

    int  idx[ITEMS];
    bool ok[ITEMS];
    #pragma unroll
    for (int j = 0; j < ITEMS; ++j) {
        idx[j] = base + j * BLKTHREADS;
        ok[j]  = idx[j] < total4;
    }

    // Phase 1: main stream loads, all independent
    float4 v[ITEMS];
    #pragma unroll
    for (int j = 0; j < ITEMS; ++j)
        if (ok[j]) v[j] = ipt[idx[j]];

    // Phase 2: scale operand loads (cached; each t_hat reused 100x, s_hat 4800x)
    float th[ITEMS], sh[ITEMS], roi[ITEMS];
    #pragma unroll
    for (int j = 0; j < ITEMS; ++j) {
        if (ok[j]) {
            const int p  = idx[j] >> 2;        // linear (b,h,w)
            const int w  = p % WIDTH;
            const int bh = p / WIDTH;          // b*HEIGHT + h
            const int b  = bh / HEIGHT;
            roi[j] = ((ROI_MASK >> w) & 1u) ? 1.0f : 0.0f;
            th[j]  = __ldg(&g_t_hat[bh]);
            sh[j]  = __ldg(&g_s_hat[b * WIDTH + w]);
        }
    }

    // Phase 3: scale and store
    #pragma unroll
    for (int j = 0; j < ITEMS; ++j) {
        if (ok[j]) {
            const float s = fmaf(th[j], sh[j], roi[j]);
            float4 r = v[j];
            r.x *= s; r.y *= s; r.z *= s; r.w *= s;
            out[idx[j]] = r;
        }
    }
}

// ---------------------------------------------------------------------------
// Launch
// ---------------------------------------------------------------------------
extern "C" void kernel_launch(void* const* d_in, const int* in_sizes, int n_in,
                              void* d_out, int out_size)
{
    // Identify inputs by size (robust to metadata ordering):
    //   ipt = B*300*25*16 (largest), t_o = B*300, s_o = B*25
    int ipt_i = 0;
    for (int k = 1; k < n_in; ++k)
        if (in_sizes[k] > in_sizes[ipt_i]) ipt_i = k;
    int a = -1, c = -1;
    for (int k = 0; k < n_in; ++k) {
        if (k == ipt_i) continue;
        if (a < 0) a = k; else c = k;
    }
    int s_i = (in_sizes[a] < in_sizes[c]) ? a : c;
    int t_i = (s_i == a) ? c : a;

    const float* s_o = (const float*)d_in[s_i];
    const float* t_o = (const float*)d_in[t_i];
    const float* ipt = (const float*)d_in[ipt_i];
    float* out = (float*)d_out;

    const int B = in_sizes[t_i] / HEIGHT;   // 1024

    // Kernel 1: normalize (B blocks x 128 threads)
    normalize_kernel<<<B, 128>>>(s_o, t_o);

    // Kernel 2: stream (4 float4 per thread, 1024 float4 per block)
    const int total4 = out_size / 4;        // 30,720,000
    const int blocks = (total4 + TILE4 - 1) / TILE4;   // 30,000
    scale_mul_kernel<<<blocks, BLKTHREADS>>>((const float4*)ipt, (float4*)out, total4);
}